// round 7
// baseline (speedup 1.0000x reference)
#include <cuda_runtime.h>
#include <cuda_bf16.h>
#include <cstdint>

#define B_ROWS    16384
#define KDIM      192
#define CDIM      256

// ===================== scratch =====================
__device__ __nv_bfloat16 g_Xhi[B_ROWS * KDIM];
__device__ __nv_bfloat16 g_Xlo[B_ROWS * KDIM];
__device__ __nv_bfloat16 g_Whi[CDIM * KDIM];
__device__ __nv_bfloat16 g_Wlo[CDIM * KDIM];

__device__ __forceinline__ void store_split(int idx, float x) {
    __nv_bfloat16 h = __float2bfloat16(x);
    float r = x - __bfloat162float(h);
    g_Xhi[idx] = h;
    g_Xlo[idx] = __float2bfloat16(r);
}

__device__ __forceinline__ uint32_t pack_bf16(float a, float b) {
    __nv_bfloat162 t = __floats2bfloat162_rn(a, b);
    return *(uint32_t*)&t;
}

// ============================================================
// Kernel A: W-conv blocks FIRST (no tail wave), then gather
// ============================================================
#define WCONV_BLOCKS  12
#define GATHER_BLOCKS (B_ROWS / 8)

__global__ void __launch_bounds__(256) gather_kernel(
    const int*   __restrict__ user_input,
    const float* __restrict__ emb,
    const int*   __restrict__ sc_country_idx,
    const float* __restrict__ sc_country_emb,
    const int*   __restrict__ sc_device_idx,
    const float* __restrict__ sc_device_emb,
    const int*   __restrict__ mf_tags_idx,
    const float* __restrict__ mf_tags_emb,
    const int*   __restrict__ mf_history_idx,
    const float* __restrict__ mf_history_emb,
    const float* __restrict__ fc_w)
{
    if (blockIdx.x < WCONV_BLOCKS) {
        int gid = blockIdx.x * 256 + threadIdx.x;   // 0..3071
        const float4* w4 = (const float4*)fc_w;
        #pragma unroll
        for (int j = 0; j < 4; j++) {
            int i4 = gid + j * 3072;                // 12288 float4 total
            float4 v = w4[i4];
            __nv_bfloat16 h0 = __float2bfloat16(v.x);
            __nv_bfloat16 h1 = __float2bfloat16(v.y);
            __nv_bfloat16 h2 = __float2bfloat16(v.z);
            __nv_bfloat16 h3 = __float2bfloat16(v.w);
            uint2 hi, lo;
            hi.x = pack_bf16(__bfloat162float(h0), __bfloat162float(h1));
            hi.y = pack_bf16(__bfloat162float(h2), __bfloat162float(h3));
            lo.x = pack_bf16(v.x - __bfloat162float(h0), v.y - __bfloat162float(h1));
            lo.y = pack_bf16(v.z - __bfloat162float(h2), v.w - __bfloat162float(h3));
            ((uint2*)g_Whi)[i4] = hi;
            ((uint2*)g_Wlo)[i4] = lo;
        }
        return;
    }

    int row  = ((blockIdx.x - WCONV_BLOCKS) * blockDim.x + threadIdx.x) >> 5;
    int lane = threadIdx.x & 31;

    int u = user_input[row];
    int base = row * KDIM;

    float2 e = ((const float2*)(emb + (size_t)u * 64))[lane];
    store_split(base + 2 * lane,     e.x);
    store_split(base + 2 * lane + 1, e.y);

    int ci = sc_country_idx[u];
    int di = sc_device_idx[u];
    store_split(base + 64 + lane, sc_country_emb[(size_t)ci * 32 + lane]);
    store_split(base + 96 + lane, sc_device_emb[(size_t)di * 32 + lane]);

    int ti = (lane < 20) ? mf_tags_idx[(size_t)u * 20 + lane] : 0;
    float tacc = 0.f;
    #pragma unroll
    for (int t = 0; t < 20; t++) {
        int id = __shfl_sync(0xffffffffu, ti, t);
        tacc += mf_tags_emb[(size_t)id * 32 + lane];
    }
    store_split(base + 128 + lane, tacc * (1.f / 20.f));

    int hA = mf_history_idx[(size_t)u * 50 + lane];
    int hB = (lane < 18) ? mf_history_idx[(size_t)u * 50 + 32 + lane] : 0;
    float a0 = 0.f, a1 = 0.f;
    #pragma unroll
    for (int t = 0; t < 32; t++) {
        int id = __shfl_sync(0xffffffffu, hA, t);
        a0 += mf_history_emb[(size_t)id * 32 + lane];
    }
    #pragma unroll
    for (int t = 0; t < 18; t++) {
        int id = __shfl_sync(0xffffffffu, hB, t);
        a1 += mf_history_emb[(size_t)id * 32 + lane];
    }
    store_split(base + 160 + lane, (a0 + a1) * (1.f / 50.f));
}

// ============================================================
// Kernel B: HMMA GEMM + bias/relu/LN — 2 CTAs/SM
//   CTA tile 64x256, 256 thr = 8 warps (2 m x 4 n), warp 32x64
//   smem 83KB: X(hi,lo) one K-half + one W region, streamed
// ============================================================
#define GEMM_THREADS 256
#define TILE_M    64
#define STRIDE_B  208
#define XSZ       (TILE_M * STRIDE_B)    // 13312
#define OFF_XHI   0
#define OFF_XLO   XSZ
#define OFF_W     (2 * XSZ)              // 26624
#define WSZ       (256 * STRIDE_B)       // 53248
#define OFF_PAR   (OFF_W + WSZ)          // 79872
#define SMEM_SZ   (OFF_PAR + 3 * 256 * 4)// 82944
#define YS_STRIDE 260                    // 64*260*4 = 66560 <= 79872 (reuse)

__device__ __forceinline__ uint32_t smem_u32(const void* p) {
    uint32_t a;
    asm("{ .reg .u64 t; cvta.to.shared.u64 t, %1; cvt.u32.u64 %0, t; }"
        : "=r"(a) : "l"(p));
    return a;
}
__device__ __forceinline__ void cp_async16(uint32_t dst, const void* src) {
    asm volatile("cp.async.cg.shared.global [%0], [%1], 16;"
        :: "r"(dst), "l"(src));
}
#define CP_COMMIT()   asm volatile("cp.async.commit_group;" ::: "memory")
#define CP_WAIT_ALL() asm volatile("cp.async.wait_all;" ::: "memory")

__device__ __forceinline__ void ldsm_x4(uint32_t r[4], uint32_t addr) {
    asm volatile("ldmatrix.sync.aligned.m8n8.x4.shared.b16 {%0,%1,%2,%3}, [%4];"
        : "=r"(r[0]), "=r"(r[1]), "=r"(r[2]), "=r"(r[3]) : "r"(addr));
}
__device__ __forceinline__ void mma16816(float* d, const uint32_t* a,
                                         uint32_t b0, uint32_t b1) {
    asm volatile(
        "mma.sync.aligned.m16n8k16.row.col.f32.bf16.bf16.f32 "
        "{%0,%1,%2,%3}, {%4,%5,%6,%7}, {%8,%9}, {%0,%1,%2,%3};"
        : "+f"(d[0]), "+f"(d[1]), "+f"(d[2]), "+f"(d[3])
        : "r"(a[0]), "r"(a[1]), "r"(a[2]), "r"(a[3]), "r"(b0), "r"(b1));
}

// stage one W region (hi or lo), one K-half: 256 rows x 12 uint4
__device__ __forceinline__ void cp_w_region(uint32_t sb,
                                            const __nv_bfloat16* src,
                                            int half, int tid) {
    #pragma unroll
    for (int it = 0; it < 12; it++) {
        int i = tid + it * GEMM_THREADS;
        int n = i / 12, q = i - n * 12;
        cp_async16(sb + OFF_W + (uint32_t)(n * STRIDE_B + q * 16),
                   src + (size_t)n * KDIM + half * 96 + q * 8);
    }
}
// stage one X region (hi or lo), one K-half: 64 rows x 12 uint4
__device__ __forceinline__ void cp_x_region(uint32_t sb, uint32_t off,
                                            const __nv_bfloat16* src,
                                            int m_base, int half, int tid) {
    #pragma unroll
    for (int it = 0; it < 3; it++) {
        int i = tid + it * GEMM_THREADS;
        int r = i / 12, q = i - r * 12;
        cp_async16(sb + off + (uint32_t)(r * STRIDE_B + q * 16),
                   src + (size_t)(m_base + r) * KDIM + half * 96 + q * 8);
    }
}

__device__ __forceinline__ void mma_pass(uint32_t xb, uint32_t wb,
                                         float acc[2][8][4]) {
    #pragma unroll
    for (int s = 0; s < 6; s++) {
        uint32_t ko = (uint32_t)s * 32;
        uint32_t a0[4], a1[4], b[4][4];
        ldsm_x4(a0, xb + ko);
        ldsm_x4(a1, xb + 16 * STRIDE_B + ko);
        #pragma unroll
        for (int j = 0; j < 4; j++)
            ldsm_x4(b[j], wb + j * 16 * STRIDE_B + ko);
        #pragma unroll
        for (int j = 0; j < 4; j++) {
            mma16816(acc[0][2*j],     a0, b[j][0], b[j][2]);
            mma16816(acc[0][2*j + 1], a0, b[j][1], b[j][3]);
            mma16816(acc[1][2*j],     a1, b[j][0], b[j][2]);
            mma16816(acc[1][2*j + 1], a1, b[j][1], b[j][3]);
        }
    }
}

__global__ void __launch_bounds__(GEMM_THREADS, 2) gemm_ln_mma_kernel(
    const float* __restrict__ fc_b,
    const float* __restrict__ ln_g,
    const float* __restrict__ ln_b,
    float*       __restrict__ out)    // [B_ROWS][256]
{
    extern __shared__ __align__(16) char smem[];
    const uint32_t sb = smem_u32(smem);
    const int tid  = threadIdx.x;
    const int lane = tid & 31;
    const int w    = tid >> 5;
    const int mgrp = w >> 2;      // 0..1 : rows mgrp*32..+31
    const int ngrp = w & 3;       // 0..3 : cols ngrp*64..+63
    const int m_base = blockIdx.x * TILE_M;

    float* sPar = (float*)(smem + OFF_PAR);
    sPar[tid]       = fc_b[tid];
    sPar[256 + tid] = ln_g[tid];
    sPar[512 + tid] = ln_b[tid];

    float acc[2][8][4];
    #pragma unroll
    for (int i = 0; i < 2; i++)
        #pragma unroll
        for (int j = 0; j < 8; j++)
            #pragma unroll
            for (int k = 0; k < 4; k++) acc[i][j][k] = 0.f;

    const int rk = lane & 15;
    const uint32_t kbyte = (uint32_t)((lane >> 4) << 4);
    const uint32_t xrow = (uint32_t)((mgrp * 32 + rk) * STRIDE_B) + kbyte;
    const uint32_t wrow = (uint32_t)((ngrp * 64 + rk) * STRIDE_B) + kbyte;

    #pragma unroll
    for (int half = 0; half < 2; half++) {
        // stage X(hi,lo) + WHI for this K-half
        cp_x_region(sb, OFF_XHI, g_Xhi, m_base, half, tid);
        cp_x_region(sb, OFF_XLO, g_Xlo, m_base, half, tid);
        cp_w_region(sb, g_Whi, half, tid);
        CP_COMMIT();
        CP_WAIT_ALL();
        __syncthreads();

        mma_pass(sb + OFF_XHI + xrow, sb + OFF_W + wrow, acc);   // Ahi*Whi
        mma_pass(sb + OFF_XLO + xrow, sb + OFF_W + wrow, acc);   // Alo*Whi

        __syncthreads();                 // done reading WHI
        cp_w_region(sb, g_Wlo, half, tid);
        CP_COMMIT();
        CP_WAIT_ALL();
        __syncthreads();

        mma_pass(sb + OFF_XHI + xrow, sb + OFF_W + wrow, acc);   // Ahi*Wlo

        __syncthreads();                 // done reading X/W before restage
    }

    // ---- epilogue: fragments -> ys smem (bias+relu) ----
    float* ys = (float*)smem;   // [64][YS_STRIDE]
    {
        const int r0 = mgrp * 32 + (lane >> 2);
        const int c0 = ngrp * 64 + (lane & 3) * 2;
        #pragma unroll
        for (int mf = 0; mf < 2; mf++)
            #pragma unroll
            for (int nf = 0; nf < 8; nf++) {
                int r = r0 + mf * 16;
                int c = c0 + nf * 8;
                float b0 = sPar[c], b1 = sPar[c + 1];
                float2 v0 = make_float2(fmaxf(acc[mf][nf][0] + b0, 0.f),
                                        fmaxf(acc[mf][nf][1] + b1, 0.f));
                float2 v1 = make_float2(fmaxf(acc[mf][nf][2] + b0, 0.f),
                                        fmaxf(acc[mf][nf][3] + b1, 0.f));
                *(float2*)&ys[r * YS_STRIDE + c]       = v0;
                *(float2*)&ys[(r + 8) * YS_STRIDE + c] = v1;
            }
    }
    __syncthreads();

    // ---- LayerNorm: warp w handles rows w*8 .. w*8+7 ----
    #pragma unroll
    for (int rr = 0; rr < 8; rr++) {
        int r = w * 8 + rr;
        float v[8];
        float sum = 0.f, ss = 0.f;
        #pragma unroll
        for (int j = 0; j < 8; j++) {
            v[j] = ys[r * YS_STRIDE + lane + 32 * j];
            sum += v[j];
            ss  += v[j] * v[j];
        }
        #pragma unroll
        for (int o = 16; o; o >>= 1) {
            sum += __shfl_xor_sync(0xffffffffu, sum, o);
            ss  += __shfl_xor_sync(0xffffffffu, ss,  o);
        }
        float mean = sum * (1.f / 256.f);
        float var  = ss * (1.f / 256.f) - mean * mean;
        float rstd = rsqrtf(var + 1e-5f);
        float* orow = out + (size_t)(m_base + r) * CDIM;
        #pragma unroll
        for (int j = 0; j < 8; j++) {
            int c = lane + 32 * j;
            orow[c] = (v[j] - mean) * rstd * sPar[256 + c] + sPar[512 + c];
        }
    }
}

// ============================================================
extern "C" void kernel_launch(void* const* d_in, const int* in_sizes, int n_in,
                              void* d_out, int out_size) {
    (void)in_sizes; (void)n_in; (void)out_size;
    const int*   user_input      = (const int*)  d_in[0];
    const float* emb             = (const float*)d_in[1];
    const int*   sc_country_idx  = (const int*)  d_in[2];
    const float* sc_country_emb  = (const float*)d_in[3];
    const int*   sc_device_idx   = (const int*)  d_in[4];
    const float* sc_device_emb   = (const float*)d_in[5];
    const int*   mf_tags_idx     = (const int*)  d_in[6];
    const float* mf_tags_emb     = (const float*)d_in[7];
    const int*   mf_history_idx  = (const int*)  d_in[8];
    const float* mf_history_emb  = (const float*)d_in[9];
    const float* fc_w            = (const float*)d_in[10];
    const float* fc_b            = (const float*)d_in[11];
    const float* ln_g            = (const float*)d_in[12];
    const float* ln_b            = (const float*)d_in[13];
    float* out = (float*)d_out;

    gather_kernel<<<GATHER_BLOCKS + WCONV_BLOCKS, 256>>>(
        user_input, emb,
        sc_country_idx, sc_country_emb,
        sc_device_idx,  sc_device_emb,
        mf_tags_idx,    mf_tags_emb,
        mf_history_idx, mf_history_emb,
        fc_w);

    cudaFuncSetAttribute(gemm_ln_mma_kernel,
                         cudaFuncAttributeMaxDynamicSharedMemorySize, SMEM_SZ);
    gemm_ln_mma_kernel<<<B_ROWS / TILE_M, GEMM_THREADS, SMEM_SZ>>>(fc_b, ln_g, ln_b, out);
}

// round 8
// speedup vs baseline: 2.6610x; 2.6610x over previous
#include <cuda_runtime.h>
#include <cuda_fp16.h>
#include <cstdint>

#define B_ROWS    16384
#define KDIM      192
#define CDIM      256

// ===================== scratch (fp16 X and W) =====================
__device__ __half g_X[B_ROWS * KDIM];
__device__ __half g_W[CDIM * KDIM];

// ============================================================
// Kernel A: W-conv blocks FIRST, then gather (one warp per row)
// ============================================================
#define WCONV_BLOCKS  12
#define GATHER_BLOCKS (B_ROWS / 8)

__global__ void __launch_bounds__(256) gather_kernel(
    const int*   __restrict__ user_input,
    const float* __restrict__ emb,
    const int*   __restrict__ sc_country_idx,
    const float* __restrict__ sc_country_emb,
    const int*   __restrict__ sc_device_idx,
    const float* __restrict__ sc_device_emb,
    const int*   __restrict__ mf_tags_idx,
    const float* __restrict__ mf_tags_emb,
    const int*   __restrict__ mf_history_idx,
    const float* __restrict__ mf_history_emb,
    const float* __restrict__ fc_w)
{
    if (blockIdx.x < WCONV_BLOCKS) {
        // ---- W conversion: fp32 -> fp16 ----
        int gid = blockIdx.x * 256 + threadIdx.x;   // 0..3071
        const float4* w4 = (const float4*)fc_w;
        #pragma unroll
        for (int j = 0; j < 4; j++) {
            int i4 = gid + j * 3072;                // 12288 float4 total
            float4 v = w4[i4];
            __half2 p0 = __floats2half2_rn(v.x, v.y);
            __half2 p1 = __floats2half2_rn(v.z, v.w);
            uint2 o;
            o.x = *(uint32_t*)&p0;
            o.y = *(uint32_t*)&p1;
            ((uint2*)g_W)[i4] = o;
        }
        return;
    }

    int row  = ((blockIdx.x - WCONV_BLOCKS) * blockDim.x + threadIdx.x) >> 5;
    int lane = threadIdx.x & 31;

    int u = user_input[row];
    int base = row * KDIM;

    // main embedding: 64 floats -> half2
    float2 e = ((const float2*)(emb + (size_t)u * 64))[lane];
    ((__half2*)(g_X + base))[lane] = __floats2half2_rn(e.x, e.y);

    // scalar side features
    int ci = sc_country_idx[u];
    int di = sc_device_idx[u];
    g_X[base + 64 + lane] = __float2half_rn(sc_country_emb[(size_t)ci * 32 + lane]);
    g_X[base + 96 + lane] = __float2half_rn(sc_device_emb[(size_t)di * 32 + lane]);

    // tags: mean over 20
    int ti = (lane < 20) ? mf_tags_idx[(size_t)u * 20 + lane] : 0;
    float tacc = 0.f;
    #pragma unroll
    for (int t = 0; t < 20; t++) {
        int id = __shfl_sync(0xffffffffu, ti, t);
        tacc += mf_tags_emb[(size_t)id * 32 + lane];
    }
    g_X[base + 128 + lane] = __float2half_rn(tacc * (1.f / 20.f));

    // history: mean over 50
    int hA = mf_history_idx[(size_t)u * 50 + lane];
    int hB = (lane < 18) ? mf_history_idx[(size_t)u * 50 + 32 + lane] : 0;
    float a0 = 0.f, a1 = 0.f;
    #pragma unroll
    for (int t = 0; t < 32; t++) {
        int id = __shfl_sync(0xffffffffu, hA, t);
        a0 += mf_history_emb[(size_t)id * 32 + lane];
    }
    #pragma unroll
    for (int t = 0; t < 18; t++) {
        int id = __shfl_sync(0xffffffffu, hB, t);
        a1 += mf_history_emb[(size_t)id * 32 + lane];
    }
    g_X[base + 160 + lane] = __float2half_rn((a0 + a1) * (1.f / 50.f));
}

// ============================================================
// Kernel B: single-pass fp16 HMMA GEMM + bias/relu/LN
//   512 thr = 16 warps (4 m x 4 n), warp tile 32x64, CTA 128x256
//   full K=192 staged once via cp.async; 12 straight k-steps
// ============================================================
#define GEMM_THREADS 512
#define STRIDE_B  400                    // 192 half = 384B + 16 pad
#define XSZ       (128 * STRIDE_B)       // 51200
#define OFF_W     XSZ
#define WSZ       (256 * STRIDE_B)       // 102400
#define OFF_PAR   (OFF_W + WSZ)          // 153600
#define SMEM_SZ   (OFF_PAR + 3 * 256 * 4)// 156672
#define YS_STRIDE 260

__device__ __forceinline__ uint32_t smem_u32(const void* p) {
    uint32_t a;
    asm("{ .reg .u64 t; cvta.to.shared.u64 t, %1; cvt.u32.u64 %0, t; }"
        : "=r"(a) : "l"(p));
    return a;
}
__device__ __forceinline__ void cp_async16(uint32_t dst, const void* src) {
    asm volatile("cp.async.cg.shared.global [%0], [%1], 16;"
        :: "r"(dst), "l"(src));
}
#define CP_COMMIT()   asm volatile("cp.async.commit_group;" ::: "memory")
#define CP_WAIT_ALL() asm volatile("cp.async.wait_all;" ::: "memory")

__device__ __forceinline__ void ldsm_x4(uint32_t r[4], uint32_t addr) {
    asm volatile("ldmatrix.sync.aligned.m8n8.x4.shared.b16 {%0,%1,%2,%3}, [%4];"
        : "=r"(r[0]), "=r"(r[1]), "=r"(r[2]), "=r"(r[3]) : "r"(addr));
}
__device__ __forceinline__ void mma16816(float* d, const uint32_t* a,
                                         uint32_t b0, uint32_t b1) {
    asm volatile(
        "mma.sync.aligned.m16n8k16.row.col.f32.f16.f16.f32 "
        "{%0,%1,%2,%3}, {%4,%5,%6,%7}, {%8,%9}, {%0,%1,%2,%3};"
        : "+f"(d[0]), "+f"(d[1]), "+f"(d[2]), "+f"(d[3])
        : "r"(a[0]), "r"(a[1]), "r"(a[2]), "r"(a[3]), "r"(b0), "r"(b1));
}

__device__ __forceinline__ void load_frags(uint32_t xb, uint32_t wb, uint32_t ko,
                                           uint32_t a0[4], uint32_t a1[4],
                                           uint32_t b[4][4]) {
    ldsm_x4(a0, xb + ko);
    ldsm_x4(a1, xb + 16 * STRIDE_B + ko);
    #pragma unroll
    for (int j = 0; j < 4; j++)
        ldsm_x4(b[j], wb + j * 16 * STRIDE_B + ko);
}

__global__ void __launch_bounds__(GEMM_THREADS, 1) gemm_ln_mma_kernel(
    const float* __restrict__ fc_b,
    const float* __restrict__ ln_g,
    const float* __restrict__ ln_b,
    float*       __restrict__ out)    // [B_ROWS][256]
{
    extern __shared__ __align__(16) char smem[];
    const uint32_t sb = smem_u32(smem);
    const int tid  = threadIdx.x;
    const int lane = tid & 31;
    const int w    = tid >> 5;
    const int mgrp = w >> 2;      // rows mgrp*32..+31
    const int ngrp = w & 3;       // cols ngrp*64..+63
    const int m_base = blockIdx.x * 128;

    float* sPar = (float*)(smem + OFF_PAR);

    // ---- stage X rows (128 x 24 uint4) + W (256 x 24 uint4) ----
    #pragma unroll
    for (int it = 0; it < 6; it++) {                 // 3072 / 512
        int i = tid + it * GEMM_THREADS;
        int r = i / 24, q = i - r * 24;
        cp_async16(sb + (uint32_t)(r * STRIDE_B + q * 16),
                   g_X + (size_t)(m_base + r) * KDIM + q * 8);
    }
    #pragma unroll
    for (int it = 0; it < 12; it++) {                // 6144 / 512
        int i = tid + it * GEMM_THREADS;
        int n = i / 24, q = i - n * 24;
        cp_async16(sb + OFF_W + (uint32_t)(n * STRIDE_B + q * 16),
                   g_W + (size_t)n * KDIM + q * 8);
    }
    CP_COMMIT();

    if (tid < 256) {
        sPar[tid]       = fc_b[tid];
        sPar[256 + tid] = ln_g[tid];
        sPar[512 + tid] = ln_b[tid];
    }

    CP_WAIT_ALL();
    __syncthreads();

    float acc[2][8][4];
    #pragma unroll
    for (int i = 0; i < 2; i++)
        #pragma unroll
        for (int j = 0; j < 8; j++)
            #pragma unroll
            for (int k = 0; k < 4; k++) acc[i][j][k] = 0.f;

    const int rk = lane & 15;
    const uint32_t kbyte = (uint32_t)((lane >> 4) << 4);
    const uint32_t xb = sb + (uint32_t)((mgrp * 32 + rk) * STRIDE_B) + kbyte;
    const uint32_t wb = sb + OFF_W + (uint32_t)((ngrp * 64 + rk) * STRIDE_B) + kbyte;

    // ---- 12 k16-steps, double-buffered fragments ----
    uint32_t A0[2][4], A1[2][4], Bf[2][4][4];
    load_frags(xb, wb, 0, A0[0], A1[0], Bf[0]);
    #pragma unroll
    for (int s = 0; s < 12; s++) {
        int cur = s & 1, nxt = cur ^ 1;
        if (s < 11)
            load_frags(xb, wb, (uint32_t)(s + 1) * 32, A0[nxt], A1[nxt], Bf[nxt]);
        #pragma unroll
        for (int j = 0; j < 4; j++) {
            mma16816(acc[0][2*j],     A0[cur], Bf[cur][j][0], Bf[cur][j][2]);
            mma16816(acc[0][2*j + 1], A0[cur], Bf[cur][j][1], Bf[cur][j][3]);
            mma16816(acc[1][2*j],     A1[cur], Bf[cur][j][0], Bf[cur][j][2]);
            mma16816(acc[1][2*j + 1], A1[cur], Bf[cur][j][1], Bf[cur][j][3]);
        }
    }
    __syncthreads();   // all smem reads done before ys overwrite

    // ---- epilogue: fragments -> ys smem (bias+relu) ----
    float* ys = (float*)smem;   // [128][YS_STRIDE]
    {
        const int r0 = mgrp * 32 + (lane >> 2);
        const int c0 = ngrp * 64 + (lane & 3) * 2;
        #pragma unroll
        for (int mf = 0; mf < 2; mf++)
            #pragma unroll
            for (int nf = 0; nf < 8; nf++) {
                int r = r0 + mf * 16;
                int c = c0 + nf * 8;
                float b0 = sPar[c], b1 = sPar[c + 1];
                float2 v0 = make_float2(fmaxf(acc[mf][nf][0] + b0, 0.f),
                                        fmaxf(acc[mf][nf][1] + b1, 0.f));
                float2 v1 = make_float2(fmaxf(acc[mf][nf][2] + b0, 0.f),
                                        fmaxf(acc[mf][nf][3] + b1, 0.f));
                *(float2*)&ys[r * YS_STRIDE + c]       = v0;
                *(float2*)&ys[(r + 8) * YS_STRIDE + c] = v1;
            }
    }
    __syncthreads();

    // ---- LayerNorm: warp w handles rows w*8 .. w*8+7 ----
    #pragma unroll
    for (int rr = 0; rr < 8; rr++) {
        int r = w * 8 + rr;
        float v[8];
        float sum = 0.f, ss = 0.f;
        #pragma unroll
        for (int j = 0; j < 8; j++) {
            v[j] = ys[r * YS_STRIDE + lane + 32 * j];
            sum += v[j];
            ss  += v[j] * v[j];
        }
        #pragma unroll
        for (int o = 16; o; o >>= 1) {
            sum += __shfl_xor_sync(0xffffffffu, sum, o);
            ss  += __shfl_xor_sync(0xffffffffu, ss,  o);
        }
        float mean = sum * (1.f / 256.f);
        float var  = ss * (1.f / 256.f) - mean * mean;
        float rstd = rsqrtf(var + 1e-5f);
        float* orow = out + (size_t)(m_base + r) * CDIM;
        #pragma unroll
        for (int j = 0; j < 8; j++) {
            int c = lane + 32 * j;
            orow[c] = (v[j] - mean) * rstd * sPar[256 + c] + sPar[512 + c];
        }
    }
}

// ============================================================
extern "C" void kernel_launch(void* const* d_in, const int* in_sizes, int n_in,
                              void* d_out, int out_size) {
    (void)in_sizes; (void)n_in; (void)out_size;
    const int*   user_input      = (const int*)  d_in[0];
    const float* emb             = (const float*)d_in[1];
    const int*   sc_country_idx  = (const int*)  d_in[2];
    const float* sc_country_emb  = (const float*)d_in[3];
    const int*   sc_device_idx   = (const int*)  d_in[4];
    const float* sc_device_emb   = (const float*)d_in[5];
    const int*   mf_tags_idx     = (const int*)  d_in[6];
    const float* mf_tags_emb     = (const float*)d_in[7];
    const int*   mf_history_idx  = (const int*)  d_in[8];
    const float* mf_history_emb  = (const float*)d_in[9];
    const float* fc_w            = (const float*)d_in[10];
    const float* fc_b            = (const float*)d_in[11];
    const float* ln_g            = (const float*)d_in[12];
    const float* ln_b            = (const float*)d_in[13];
    float* out = (float*)d_out;

    gather_kernel<<<GATHER_BLOCKS + WCONV_BLOCKS, 256>>>(
        user_input, emb,
        sc_country_idx, sc_country_emb,
        sc_device_idx,  sc_device_emb,
        mf_tags_idx,    mf_tags_emb,
        mf_history_idx, mf_history_emb,
        fc_w);

    cudaFuncSetAttribute(gemm_ln_mma_kernel,
                         cudaFuncAttributeMaxDynamicSharedMemorySize, SMEM_SZ);
    gemm_ln_mma_kernel<<<B_ROWS / 128, GEMM_THREADS, SMEM_SZ>>>(fc_b, ln_g, ln_b, out);
}